// round 1
// baseline (speedup 1.0000x reference)
#include <cuda_runtime.h>
#include <cuda_bf16.h>

// Problem constants (padded)
#define NMAX 100352          // >= 100000 nodes
#define THREADS 256

// Scratch (device globals: allocation-free rule)
__device__ float g_hx1[NMAX * 32];   // transformed layer-1 features (h*ns)@W1
__device__ float g_agg1[NMAX * 32];  // layer-1 aggregation accumulator
__device__ float g_h2x[NMAX * 16];   // transformed layer-2 features
__device__ float g_ns[NMAX];         // out-degree^-0.5 (src norm)
__device__ float g_nd[NMAX];         // in-degree^-0.5  (dst norm)

// ---------------------------------------------------------------------------
// K0: zero all accumulators + output (runs every launch -> deterministic)
__global__ void k_zero(float* __restrict__ out, int n) {
    int i = blockIdx.x * blockDim.x + threadIdx.x;
    int n32 = n * 32;
    if (i < n32) g_agg1[i] = 0.0f;
    if (i < n * 16) out[i] = 0.0f;
    if (i < n) { g_ns[i] = 0.0f; g_nd[i] = 0.0f; }
}

// K1: degree counts via atomics
__global__ void k_deg(const int* __restrict__ src, const int* __restrict__ dst, int e) {
    int i = blockIdx.x * blockDim.x + threadIdx.x;
    if (i >= e) return;
    atomicAdd(&g_ns[src[i]], 1.0f);
    atomicAdd(&g_nd[dst[i]], 1.0f);
}

// K2: deg -> rsqrt(clip(deg,1))
__global__ void k_norm(int n) {
    int i = blockIdx.x * blockDim.x + threadIdx.x;
    if (i >= n) return;
    g_ns[i] = rsqrtf(fmaxf(g_ns[i], 1.0f));
    g_nd[i] = rsqrtf(fmaxf(g_nd[i], 1.0f));
}

// K3: hx1[n,:] = (features[n,:] * ns[n]) @ W1   (one thread per node)
__global__ void k_xform1(const float* __restrict__ feat,
                         const float* __restrict__ W1, int n) {
    __shared__ float4 sW[32 * 8];  // 32x32 as float4 rows
    for (int j = threadIdx.x; j < 32 * 8; j += blockDim.x)
        sW[j] = ((const float4*)W1)[j];
    __syncthreads();

    int node = blockIdx.x * blockDim.x + threadIdx.x;
    if (node >= n) return;

    float4 acc[8];
#pragma unroll
    for (int j = 0; j < 8; j++) acc[j] = make_float4(0.f, 0.f, 0.f, 0.f);

    const float* f = feat + (size_t)node * 32;
#pragma unroll
    for (int k = 0; k < 32; k++) {
        float fk = f[k];
#pragma unroll
        for (int j = 0; j < 8; j++) {
            float4 w = sW[k * 8 + j];
            acc[j].x += fk * w.x; acc[j].y += fk * w.y;
            acc[j].z += fk * w.z; acc[j].w += fk * w.w;
        }
    }
    float s = g_ns[node];
    float4* outr = (float4*)(g_hx1 + (size_t)node * 32);
#pragma unroll
    for (int j = 0; j < 8; j++) {
        acc[j].x *= s; acc[j].y *= s; acc[j].z *= s; acc[j].w *= s;
        outr[j] = acc[j];
    }
}

// K4: edge aggregation, layer 1 (32-wide): 8 threads per edge, float4 each
__global__ void k_edge1(const int* __restrict__ src, const int* __restrict__ dst,
                        const float* __restrict__ ew, int e) {
    int t = blockIdx.x * blockDim.x + threadIdx.x;
    if (t >= e * 8) return;
    int eid = t >> 3;
    int c = t & 7;
    int s = __ldg(src + eid);
    int d = __ldg(dst + eid);
    float w = __ldg(ew + eid);
    float4 v = *(const float4*)(g_hx1 + (size_t)s * 32 + c * 4);
    v.x *= w; v.y *= w; v.z *= w; v.w *= w;
    float* p = g_agg1 + (size_t)d * 32 + c * 4;
    asm volatile("red.global.add.v4.f32 [%0], {%1,%2,%3,%4};"
                 :: "l"(p), "f"(v.x), "f"(v.y), "f"(v.z), "f"(v.w)
                 : "memory");
}

// K5: h1 = relu(agg1*nd + b1); h2x = (h1*ns) @ W2   (one thread per node)
__global__ void k_xform2(const float* __restrict__ W2,
                         const float* __restrict__ b1, int n) {
    __shared__ float4 sW[32 * 4];  // 32x16 as float4 rows
    __shared__ float sb1[32];
    for (int j = threadIdx.x; j < 32 * 4; j += blockDim.x)
        sW[j] = ((const float4*)W2)[j];
    for (int j = threadIdx.x; j < 32; j += blockDim.x)
        sb1[j] = b1[j];
    __syncthreads();

    int node = blockIdx.x * blockDim.x + threadIdx.x;
    if (node >= n) return;

    float nd = g_nd[node];
    float ns = g_ns[node];
    float4 acc[4];
#pragma unroll
    for (int j = 0; j < 4; j++) acc[j] = make_float4(0.f, 0.f, 0.f, 0.f);

    const float* a = g_agg1 + (size_t)node * 32;
#pragma unroll
    for (int k = 0; k < 32; k++) {
        float h = fmaxf(a[k] * nd + sb1[k], 0.0f) * ns;
#pragma unroll
        for (int j = 0; j < 4; j++) {
            float4 w = sW[k * 4 + j];
            acc[j].x += h * w.x; acc[j].y += h * w.y;
            acc[j].z += h * w.z; acc[j].w += h * w.w;
        }
    }
    float4* outr = (float4*)(g_h2x + (size_t)node * 16);
#pragma unroll
    for (int j = 0; j < 4; j++) outr[j] = acc[j];
}

// K6: edge aggregation, layer 2 (16-wide): 4 threads per edge -> out (zeroed)
__global__ void k_edge2(const int* __restrict__ src, const int* __restrict__ dst,
                        const float* __restrict__ ew, float* __restrict__ out, int e) {
    int t = blockIdx.x * blockDim.x + threadIdx.x;
    if (t >= e * 4) return;
    int eid = t >> 2;
    int c = t & 3;
    int s = __ldg(src + eid);
    int d = __ldg(dst + eid);
    float w = __ldg(ew + eid);
    float4 v = *(const float4*)(g_h2x + (size_t)s * 16 + c * 4);
    v.x *= w; v.y *= w; v.z *= w; v.w *= w;
    float* p = out + (size_t)d * 16 + c * 4;
    asm volatile("red.global.add.v4.f32 [%0], {%1,%2,%3,%4};"
                 :: "l"(p), "f"(v.x), "f"(v.y), "f"(v.z), "f"(v.w)
                 : "memory");
}

// K7: out = out*nd + b2 (in-place, float4 per thread over n*4 chunks)
__global__ void k_final(float* __restrict__ out, const float* __restrict__ b2, int n) {
    int t = blockIdx.x * blockDim.x + threadIdx.x;
    if (t >= n * 4) return;
    int node = t >> 2;
    int c = t & 3;
    float nd = g_nd[node];
    float4 b = ((const float4*)b2)[c];
    float4 o = ((float4*)out)[t];
    o.x = o.x * nd + b.x; o.y = o.y * nd + b.y;
    o.z = o.z * nd + b.z; o.w = o.w * nd + b.w;
    ((float4*)out)[t] = o;
}

static inline int cdiv(long long a, int b) { return (int)((a + b - 1) / b); }

extern "C" void kernel_launch(void* const* d_in, const int* in_sizes, int n_in,
                              void* d_out, int out_size) {
    const float* feat = (const float*)d_in[0];
    const int*   src  = (const int*)d_in[1];
    const int*   dst  = (const int*)d_in[2];
    const float* ew   = (const float*)d_in[3];
    const float* W1   = (const float*)d_in[4];
    const float* b1   = (const float*)d_in[5];
    const float* W2   = (const float*)d_in[6];
    const float* b2   = (const float*)d_in[7];
    float* out = (float*)d_out;

    int n = in_sizes[0] / 32;
    int e = in_sizes[1];

    k_zero  <<<cdiv((long long)n * 32, THREADS), THREADS>>>(out, n);
    k_deg   <<<cdiv(e, THREADS), THREADS>>>(src, dst, e);
    k_norm  <<<cdiv(n, THREADS), THREADS>>>(n);
    k_xform1<<<cdiv(n, THREADS), THREADS>>>(feat, W1, n);
    k_edge1 <<<cdiv((long long)e * 8, THREADS), THREADS>>>(src, dst, ew, e);
    k_xform2<<<cdiv(n, THREADS), THREADS>>>(W2, b1, n);
    k_edge2 <<<cdiv((long long)e * 4, THREADS), THREADS>>>(src, dst, ew, out, e);
    k_final <<<cdiv((long long)n * 4, THREADS), THREADS>>>(out, b2, n);
}

// round 2
// speedup vs baseline: 1.5648x; 1.5648x over previous
#include <cuda_runtime.h>
#include <cuda_bf16.h>

#define NMAX 100352
#define THREADS 256
#define FULL 0xffffffffu

__device__ float g_hx1[NMAX * 32];   // (f*ns)@W1
__device__ float g_agg1[NMAX * 32];  // layer-1 accumulator (includes nd scale)
__device__ float g_h2x[NMAX * 16];   // (relu(agg1+b1)*ns)@W2
__device__ float g_ns[NMAX];
__device__ float g_nd[NMAX];

// K0: zero agg/norms, init out rows to b2
__global__ void k_zero(float* __restrict__ out, const float* __restrict__ b2, int n) {
    int i = blockIdx.x * blockDim.x + threadIdx.x;
    if (i < n * 32) g_agg1[i] = 0.0f;
    if (i < n * 16) out[i] = __ldg(b2 + (i & 15));
    if (i < n) { g_ns[i] = 0.0f; g_nd[i] = 0.0f; }
}

// K1: degree counts (4 edges per thread, int4 loads)
__global__ void k_deg(const int* __restrict__ src, const int* __restrict__ dst, int e) {
    int t = blockIdx.x * blockDim.x + threadIdx.x;
    int base = t * 4;
    if (base + 3 < e) {
        int4 s4 = *(const int4*)(src + base);
        int4 d4 = *(const int4*)(dst + base);
        atomicAdd(&g_ns[s4.x], 1.0f); atomicAdd(&g_ns[s4.y], 1.0f);
        atomicAdd(&g_ns[s4.z], 1.0f); atomicAdd(&g_ns[s4.w], 1.0f);
        atomicAdd(&g_nd[d4.x], 1.0f); atomicAdd(&g_nd[d4.y], 1.0f);
        atomicAdd(&g_nd[d4.z], 1.0f); atomicAdd(&g_nd[d4.w], 1.0f);
    } else {
        for (int i = base; i < e; i++) {
            atomicAdd(&g_ns[src[i]], 1.0f);
            atomicAdd(&g_nd[dst[i]], 1.0f);
        }
    }
}

// K2: deg -> rsqrt(clip(deg,1))
__global__ void k_norm(int n) {
    int i = blockIdx.x * blockDim.x + threadIdx.x;
    if (i >= n) return;
    g_ns[i] = rsqrtf(fmaxf(g_ns[i], 1.0f));
    g_nd[i] = rsqrtf(fmaxf(g_nd[i], 1.0f));
}

// K3: warp per 2 nodes/iter: hx1[n,lane] = sum_k f[n,k]*ns[n]*W1[k,lane]
__global__ void k_xform1(const float* __restrict__ feat,
                         const float* __restrict__ W1, int n) {
    int lane = threadIdx.x & 31;
    float w[32];
#pragma unroll
    for (int k = 0; k < 32; k++) w[k] = __ldg(W1 + k * 32 + lane);

    int warpId = (blockIdx.x * blockDim.x + threadIdx.x) >> 5;
    int nwarps = (gridDim.x * blockDim.x) >> 5;

    for (int base = warpId * 2; base < n; base += nwarps * 2) {
        int n0 = base, n1 = base + 1;
        bool has1 = (n1 < n);
        float f0 = feat[(size_t)n0 * 32 + lane];
        float f1 = has1 ? feat[(size_t)n1 * 32 + lane] : 0.0f;
        float acc0 = 0.f, acc1 = 0.f;
#pragma unroll
        for (int k = 0; k < 32; k++) {
            acc0 = fmaf(__shfl_sync(FULL, f0, k), w[k], acc0);
            acc1 = fmaf(__shfl_sync(FULL, f1, k), w[k], acc1);
        }
        g_hx1[(size_t)n0 * 32 + lane] = acc0 * g_ns[n0];
        if (has1) g_hx1[(size_t)n1 * 32 + lane] = acc1 * g_ns[n1];
    }
}

// K4: edge aggregation L1: 8 threads/edge, float4, nd[dst] folded into weight
__global__ void k_edge1(const int* __restrict__ src, const int* __restrict__ dst,
                        const float* __restrict__ ew, int e) {
    int t = blockIdx.x * blockDim.x + threadIdx.x;
    if (t >= e * 8) return;
    int eid = t >> 3;
    int c = t & 7;
    int s = __ldg(src + eid);
    int d = __ldg(dst + eid);
    float w = __ldg(ew + eid) * g_nd[d];
    float4 v = *(const float4*)(g_hx1 + (size_t)s * 32 + c * 4);
    v.x *= w; v.y *= w; v.z *= w; v.w *= w;
    float* p = g_agg1 + (size_t)d * 32 + c * 4;
    asm volatile("red.global.add.v4.f32 [%0], {%1,%2,%3,%4};"
                 :: "l"(p), "f"(v.x), "f"(v.y), "f"(v.z), "f"(v.w)
                 : "memory");
}

// K5: warp per node: h = relu(agg1 + b1)*ns; h2x = h @ W2 (16 out)
// lane = 16*half + j ; lane holds h_k for k=lane; half-warps split k, reduce.
__global__ void k_xform2(const float* __restrict__ W2,
                         const float* __restrict__ b1, int n) {
    int lane = threadIdx.x & 31;
    int half = lane >> 4;
    int j = lane & 15;
    float w[16];
#pragma unroll
    for (int kk = 0; kk < 16; kk++)
        w[kk] = __ldg(W2 + (half * 16 + kk) * 16 + j);
    float bl = __ldg(b1 + lane);

    int warpId = (blockIdx.x * blockDim.x + threadIdx.x) >> 5;
    int nwarps = (gridDim.x * blockDim.x) >> 5;

    for (int node = warpId; node < n; node += nwarps) {
        float a = g_agg1[(size_t)node * 32 + lane];  // already nd-scaled
        float h = fmaxf(a + bl, 0.0f) * g_ns[node];
        float acc = 0.f;
#pragma unroll
        for (int kk = 0; kk < 16; kk++)
            acc = fmaf(__shfl_sync(FULL, h, half * 16 + kk), w[kk], acc);
        acc += __shfl_xor_sync(FULL, acc, 16);
        if (half == 0) g_h2x[(size_t)node * 16 + j] = acc;
    }
}

// K6: edge aggregation L2: 4 threads/edge, nd folded; out pre-inited to b2
__global__ void k_edge2(const int* __restrict__ src, const int* __restrict__ dst,
                        const float* __restrict__ ew, float* __restrict__ out, int e) {
    int t = blockIdx.x * blockDim.x + threadIdx.x;
    if (t >= e * 4) return;
    int eid = t >> 2;
    int c = t & 3;
    int s = __ldg(src + eid);
    int d = __ldg(dst + eid);
    float w = __ldg(ew + eid) * g_nd[d];
    float4 v = *(const float4*)(g_h2x + (size_t)s * 16 + c * 4);
    v.x *= w; v.y *= w; v.z *= w; v.w *= w;
    float* p = out + (size_t)d * 16 + c * 4;
    asm volatile("red.global.add.v4.f32 [%0], {%1,%2,%3,%4};"
                 :: "l"(p), "f"(v.x), "f"(v.y), "f"(v.z), "f"(v.w)
                 : "memory");
}

static inline int cdiv(long long a, int b) { return (int)((a + b - 1) / b); }

extern "C" void kernel_launch(void* const* d_in, const int* in_sizes, int n_in,
                              void* d_out, int out_size) {
    const float* feat = (const float*)d_in[0];
    const int*   src  = (const int*)d_in[1];
    const int*   dst  = (const int*)d_in[2];
    const float* ew   = (const float*)d_in[3];
    const float* W1   = (const float*)d_in[4];
    const float* b1   = (const float*)d_in[5];
    const float* W2   = (const float*)d_in[6];
    const float* b2   = (const float*)d_in[7];
    float* out = (float*)d_out;

    int n = in_sizes[0] / 32;
    int e = in_sizes[1];

    const int XBLOCKS = 592;  // 4 blocks/SM on 148 SMs

    k_zero  <<<cdiv((long long)n * 32, THREADS), THREADS>>>(out, b2, n);
    k_deg   <<<cdiv(cdiv(e, 4), THREADS), THREADS>>>(src, dst, e);
    k_norm  <<<cdiv(n, THREADS), THREADS>>>(n);
    k_xform1<<<XBLOCKS, THREADS>>>(feat, W1, n);
    k_edge1 <<<cdiv((long long)e * 8, THREADS), THREADS>>>(src, dst, ew, e);
    k_xform2<<<XBLOCKS, THREADS>>>(W2, b1, n);
    k_edge2 <<<cdiv((long long)e * 4, THREADS), THREADS>>>(src, dst, ew, out, e);
}